// round 12
// baseline (speedup 1.0000x reference)
#include <cuda_runtime.h>
#include <cuda_bf16.h>
#include <math.h>
#include <stdint.h>

#define TSEQ 2048
#define NBATCH 2
#define CDIM 1024
#define NHEAD 16
#define DHEAD 64
#define MROWS (TSEQ*NBATCH)   // 4096

#define KCH 64                // gemm k-chunk held in smem
#define SKA 72                // smem row stride in halves (bank-conflict-free)
#define TILE_H (128*SKA)      // halves per tile
#define SMEM_G (4*TILE_H*2)   // bytes: Ah, Al, Bh, Bl (73728)
#define VPITCH 129            // fp32 pitch for V-transpose epilogue (66048 B < SMEM_G)

// attention tiling (single-buffered, high occupancy)
#define BQ 128
#define BK 64
#define SKD 72
#define SMEM_A ((2*BQ*SKD + 2*BK*SKD + 2*DHEAD*SKD)*2)

// ---------------- scratch (__device__ globals; no allocation allowed) -------
__device__ __align__(256) __nv_bfloat16 g_wh[4u*CDIM*CDIM];   // pre-split weights
__device__ __align__(256) __nv_bfloat16 g_wl[4u*CDIM*CDIM];
__device__ __align__(256) __nv_bfloat16 g_yh[MROWS*CDIM];
__device__ __align__(256) __nv_bfloat16 g_yl[MROWS*CDIM];
__device__ __align__(256) __nv_bfloat16 g_aqh[NBATCH*NHEAD*TSEQ*DHEAD];
__device__ __align__(256) __nv_bfloat16 g_aql[NBATCH*NHEAD*TSEQ*DHEAD];
__device__ __align__(256) __nv_bfloat16 g_akh[NBATCH*NHEAD*TSEQ*DHEAD];
__device__ __align__(256) __nv_bfloat16 g_akl[NBATCH*NHEAD*TSEQ*DHEAD];
__device__ __align__(256) __nv_bfloat16 g_avth[NBATCH*NHEAD*DHEAD*TSEQ]; // [d][t]
__device__ __align__(256) __nv_bfloat16 g_avtl[NBATCH*NHEAD*DHEAD*TSEQ];

// ---------------- PTX helpers ----------------------------------------------
__device__ __forceinline__ uint32_t smem_u32(const void* p) {
    uint32_t r;
    asm("{ .reg .u64 t; cvta.to.shared.u64 t, %1; cvt.u32.u64 %0, t; }"
        : "=r"(r) : "l"(p));
    return r;
}

__device__ __forceinline__ void ldsm4(uint32_t* r, uint32_t addr) {
    asm volatile("ldmatrix.sync.aligned.m8n8.x4.shared.b16 {%0,%1,%2,%3}, [%4];"
                 : "=r"(r[0]), "=r"(r[1]), "=r"(r[2]), "=r"(r[3]) : "r"(addr));
}

__device__ __forceinline__ void mma16816(float* c, const uint32_t* a, const uint32_t* b) {
    asm volatile("mma.sync.aligned.m16n8k16.row.col.f32.bf16.bf16.f32 "
                 "{%0,%1,%2,%3}, {%4,%5,%6,%7}, {%8,%9}, {%0,%1,%2,%3};"
                 : "+f"(c[0]), "+f"(c[1]), "+f"(c[2]), "+f"(c[3])
                 : "r"(a[0]), "r"(a[1]), "r"(a[2]), "r"(a[3]),
                   "r"(b[0]), "r"(b[1]));
}

__device__ __forceinline__ uint32_t pf2(float lo, float hi) {  // pack bf16x2 {lo,hi}
    uint32_t r;
    asm("cvt.rn.bf16x2.f32 %0, %1, %2;" : "=r"(r) : "f"(hi), "f"(lo));
    return r;
}
__device__ __forceinline__ uint32_t plo2(float x0, float x1, uint32_t hp) {
    float h0 = __uint_as_float(hp << 16);
    float h1 = __uint_as_float(hp & 0xffff0000u);
    return pf2(x0 - h0, x1 - h1);
}

// ---------------- tile loaders ----------------------------------------------
// fp32 source (row-major, stride CDIM) -> split hi/lo bf16 smem tiles (128x64)
__device__ __forceinline__ void load_split_f32(const float* __restrict__ src,
                                               __nv_bfloat16* smh, __nv_bfloat16* sml,
                                               int k0, int tid)
{
#pragma unroll
    for (int it = 0; it < 4; it++) {
        const int idx = it*256 + tid;
        const int row = idx >> 3;
        const int c8  = (idx & 7) * 8;
        const float4* p = (const float4*)(src + (size_t)row * CDIM + k0 + c8);
        float4 a = p[0], b = p[1];
        uint4 hi, lo;
        hi.x = pf2(a.x, a.y); lo.x = plo2(a.x, a.y, hi.x);
        hi.y = pf2(a.z, a.w); lo.y = plo2(a.z, a.w, hi.y);
        hi.z = pf2(b.x, b.y); lo.z = plo2(b.x, b.y, hi.z);
        hi.w = pf2(b.z, b.w); lo.w = plo2(b.z, b.w, hi.w);
        *(uint4*)(smh + row*SKA + c8) = hi;
        *(uint4*)(sml + row*SKA + c8) = lo;
    }
}

// pre-split bf16 sources -> smem tiles
__device__ __forceinline__ void load_pre(const __nv_bfloat16* __restrict__ sh,
                                         const __nv_bfloat16* __restrict__ sl,
                                         __nv_bfloat16* smh, __nv_bfloat16* sml,
                                         int k0, int tid)
{
#pragma unroll
    for (int it = 0; it < 4; it++) {
        const int idx = it*256 + tid;
        const int row = idx >> 3;
        const int c8  = (idx & 7) * 8;
        const size_t go = (size_t)row * CDIM + k0 + c8;
        const int so = row*SKA + c8;
        *(uint4*)(smh + so) = *(const uint4*)(sh + go);
        *(uint4*)(sml + so) = *(const uint4*)(sl + go);
    }
}

// ---------------- bf16-split GEMM (single-buffered, 2 CTA/SM) ---------------
// MODE 0: fp32 Of[m*CDIM+c];  MODE 2: bf16 split head layout;
// MODE 3: V -> transposed bf16 split [n][h][d][t] via smem transpose.
template<int MODE, bool AF32>
__device__ void gemm_mma(const float* __restrict__ Af,
                         const __nv_bfloat16* __restrict__ Ahh,
                         const __nv_bfloat16* __restrict__ Alo,
                         const __nv_bfloat16* __restrict__ Bhh,
                         const __nv_bfloat16* __restrict__ Blo,
                         const float* __restrict__ bias,
                         float* __restrict__ Of,
                         __nv_bfloat16* __restrict__ Oh,
                         __nv_bfloat16* __restrict__ Ol)
{
    extern __shared__ char dsm[];
    __nv_bfloat16* sm = (__nv_bfloat16*)dsm;
    const int tid  = threadIdx.x;
    const int lane = tid & 31;
    const int wid  = tid >> 5;
    const int m0   = blockIdx.y * 128;
    const int n0   = blockIdx.x * 128;
    const int wm   = (wid >> 2) * 64;
    const int wn   = (wid & 3) * 32;

    const uint32_t sbase = smem_u32(sm);
    const uint32_t AH = 0, AL = TILE_H*2, BH = 2*TILE_H*2, BL = 3*TILE_H*2;

    float acc[4][4][4];
#pragma unroll
    for (int mi = 0; mi < 4; mi++)
#pragma unroll
        for (int ni = 0; ni < 4; ni++)
#pragma unroll
            for (int r = 0; r < 4; r++) acc[mi][ni][r] = 0.f;

    const int lrow = lane & 15;
    const int lhi8 = (lane >> 4) * 8;

    for (int k0 = 0; k0 < CDIM; k0 += KCH) {
        __syncthreads();
        if (AF32) load_split_f32(Af + (size_t)m0*CDIM, sm, sm + TILE_H, k0, tid);
        else      load_pre(Ahh + (size_t)m0*CDIM, Alo + (size_t)m0*CDIM,
                           sm, sm + TILE_H, k0, tid);
        load_pre(Bhh + (size_t)n0*CDIM, Blo + (size_t)n0*CDIM,
                 sm + 2*TILE_H, sm + 3*TILE_H, k0, tid);
        __syncthreads();

#pragma unroll
        for (int ks = 0; ks < KCH/16; ks++) {
            const int kcol = ks*16 + lhi8;
            uint32_t ah[4][4], al[4][4], bh[4][2], bl[4][2];
#pragma unroll
            for (int mi = 0; mi < 4; mi++) {
                const uint32_t ro = (uint32_t)((wm + mi*16 + lrow)*SKA + kcol) * 2;
                ldsm4(ah[mi], sbase + AH + ro);
                ldsm4(al[mi], sbase + AL + ro);
            }
#pragma unroll
            for (int nj = 0; nj < 2; nj++) {
                const uint32_t ro = (uint32_t)((wn + nj*16 + lrow)*SKA + kcol) * 2;
                uint32_t t[4];
                ldsm4(t, sbase + BH + ro);
                bh[2*nj][0] = t[0]; bh[2*nj+1][0] = t[1];
                bh[2*nj][1] = t[2]; bh[2*nj+1][1] = t[3];
                ldsm4(t, sbase + BL + ro);
                bl[2*nj][0] = t[0]; bl[2*nj+1][0] = t[1];
                bl[2*nj][1] = t[2]; bl[2*nj+1][1] = t[3];
            }
#pragma unroll
            for (int mi = 0; mi < 4; mi++)
#pragma unroll
                for (int ni = 0; ni < 4; ni++) {
                    mma16816(acc[mi][ni], ah[mi], bh[ni]);
                    mma16816(acc[mi][ni], al[mi], bh[ni]);
                    mma16816(acc[mi][ni], ah[mi], bl[ni]);
                }
        }
    }

    const int cg = lane >> 2;
    const int ct = lane & 3;

    if (MODE == 3) {
        // ---- V epilogue: smem transpose -> [n][h][d][t] bf16 hi/lo ---------
        __syncthreads();                       // all smem tile reads done
        float* sv = (float*)dsm;               // 128 x VPITCH fp32 (66 KB)
#pragma unroll
        for (int mi = 0; mi < 4; mi++) {
#pragma unroll
            for (int ni = 0; ni < 4; ni++) {
                const int c = wn + ni*8 + ct*2;
                const float b0 = bias[n0 + c], b1 = bias[n0 + c + 1];
#pragma unroll
                for (int half = 0; half < 2; half++) {
                    const int m  = wm + mi*16 + cg + half*8;
                    const int nb = m & 1, tl = m >> 1;
                    sv[(c  )*VPITCH + nb*64 + tl] = acc[mi][ni][half*2+0] + b0;
                    sv[(c+1)*VPITCH + nb*64 + tl] = acc[mi][ni][half*2+1] + b1;
                }
            }
        }
        __syncthreads();
        // readout: one (c, nb) segment of 64 t-values per thread
        const int c = tid >> 1, nb = tid & 1;
        const int gcol = n0 + c, hh = gcol >> 6, d = gcol & 63;
        const size_t base = ((size_t)(nb*NHEAD + hh)*DHEAD + d)*TSEQ + (m0 >> 1);
        const float* row = sv + c*VPITCH + nb*64;
#pragma unroll
        for (int j = 0; j < 8; j++) {
            const float x0 = row[8*j+0], x1 = row[8*j+1], x2 = row[8*j+2], x3 = row[8*j+3];
            const float x4 = row[8*j+4], x5 = row[8*j+5], x6 = row[8*j+6], x7 = row[8*j+7];
            uint4 hv, lv;
            hv.x = pf2(x0, x1); lv.x = plo2(x0, x1, hv.x);
            hv.y = pf2(x2, x3); lv.y = plo2(x2, x3, hv.y);
            hv.z = pf2(x4, x5); lv.z = plo2(x4, x5, hv.z);
            hv.w = pf2(x6, x7); lv.w = plo2(x6, x7, hv.w);
            *(uint4*)(Oh + base + 8*j) = hv;
            *(uint4*)(Ol + base + 8*j) = lv;
        }
        return;
    }

#pragma unroll
    for (int mi = 0; mi < 4; mi++) {
#pragma unroll
        for (int ni = 0; ni < 4; ni++) {
            const int c = n0 + wn + ni*8 + ct*2;
            const float b0 = bias[c], b1 = bias[c+1];
#pragma unroll
            for (int half = 0; half < 2; half++) {
                const int m = m0 + wm + mi*16 + cg + half*8;
                const float v0 = acc[mi][ni][half*2+0] + b0;
                const float v1 = acc[mi][ni][half*2+1] + b1;
                if (MODE == 0) {
                    *(float2*)(Of + (size_t)m*CDIM + c) = make_float2(v0, v1);
                } else {   // MODE == 2
                    const int t = m >> 1, nb = m & 1;
                    const int h = c >> 6, d = c & 63;
                    const size_t idx = ((size_t)(nb*NHEAD + h)*TSEQ + t)*DHEAD + d;
                    const uint32_t hp = pf2(v0, v1);
                    *(uint32_t*)(Oh + idx) = hp;
                    *(uint32_t*)(Ol + idx) = plo2(v0, v1, hp);
                }
            }
        }
    }
}

__global__ __launch_bounds__(256, 2) void proj3_tc(
    const float* __restrict__ q,  const float* __restrict__ k,  const float* __restrict__ v,
    const float* __restrict__ bq, const float* __restrict__ bk, const float* __restrict__ bv)
{
    const int z = blockIdx.z;
    const float* A    = (z == 0) ? q  : (z == 1) ? k  : v;
    const float* bias = (z == 0) ? bq : (z == 1) ? bk : bv;
    const __nv_bfloat16* Bh = g_wh + (size_t)z * CDIM * CDIM;
    const __nv_bfloat16* Bl = g_wl + (size_t)z * CDIM * CDIM;
    if (z == 2) {
        gemm_mma<3, true>(A, nullptr, nullptr, Bh, Bl, bias,
                          nullptr, g_avth, g_avtl);
    } else {
        __nv_bfloat16* oh = (z == 0) ? g_aqh : g_akh;
        __nv_bfloat16* ol = (z == 0) ? g_aql : g_akl;
        gemm_mma<2, true>(A, nullptr, nullptr, Bh, Bl, bias,
                          nullptr, oh, ol);
    }
}

__global__ __launch_bounds__(256, 2) void oproj_tc(const float* __restrict__ bo,
                                                   float* __restrict__ out)
{
    gemm_mma<0, false>(nullptr, g_yh, g_yl,
                       g_wh + (size_t)3*CDIM*CDIM, g_wl + (size_t)3*CDIM*CDIM,
                       bo, out, nullptr, nullptr);
}

// ---------------- weight pre-split (runs once per launch) -------------------
__global__ __launch_bounds__(256) void split_w(const float* __restrict__ Wq,
                                               const float* __restrict__ Wk,
                                               const float* __restrict__ Wv,
                                               const float* __restrict__ Wo)
{
    const int z = blockIdx.z;
    const float* s = (z == 0) ? Wq : (z == 1) ? Wk : (z == 2) ? Wv : Wo;
    const size_t off = (size_t)z * CDIM * CDIM;
    const size_t i = ((size_t)blockIdx.x * blockDim.x + threadIdx.x) * 4;
    float4 vv = *(const float4*)(s + i);
    uint2 hi, lo;
    hi.x = pf2(vv.x, vv.y); lo.x = plo2(vv.x, vv.y, hi.x);
    hi.y = pf2(vv.z, vv.w); lo.y = plo2(vv.z, vv.w, hi.y);
    *(uint2*)(g_wh + off + i) = hi;
    *(uint2*)(g_wl + off + i) = lo;
}

// ---------------- tensor-core flash attention (single-buffered) -------------
__global__ __launch_bounds__(256) void attn_tc(const int* __restrict__ key_length)
{
    extern __shared__ __nv_bfloat16 as[];
    const int QH = 0, QL = BQ*SKD, KH = 2*BQ*SKD, KL = KH + BK*SKD,
              VH = KL + BK*SKD, VL = VH + DHEAD*SKD;

    const int tid = threadIdx.x, lane = tid & 31, wid = tid >> 5;
    const int n = blockIdx.z, h = blockIdx.y;
    const int q0 = blockIdx.x * BQ;
    const int keylen = key_length[n];
    const size_t hb = (size_t)(n*NHEAD + h);

    const __nv_bfloat16* Qhp = g_aqh + hb*TSEQ*DHEAD;
    const __nv_bfloat16* Qlp = g_aql + hb*TSEQ*DHEAD;
    const __nv_bfloat16* Khp = g_akh + hb*TSEQ*DHEAD;
    const __nv_bfloat16* Klp = g_akl + hb*TSEQ*DHEAD;
    const __nv_bfloat16* Vhp = g_avth + hb*DHEAD*TSEQ;
    const __nv_bfloat16* Vlp = g_avtl + hb*DHEAD*TSEQ;

    // load Q once (128x64 hi+lo)
#pragma unroll
    for (int it = 0; it < 4; it++) {
        int idx = it*256 + tid;
        int r = idx >> 3, c8 = (idx & 7) * 8;
        *(uint4*)(as + QH + r*SKD + c8) = *(const uint4*)(Qhp + (size_t)(q0+r)*DHEAD + c8);
        *(uint4*)(as + QL + r*SKD + c8) = *(const uint4*)(Qlp + (size_t)(q0+r)*DHEAD + c8);
    }

    const uint32_t sb = smem_u32(as);
    const int wm = wid * 16;
    const int lrow = lane & 15, lhi8 = (lane >> 4) * 8;
    const int cg = lane >> 2, ct = lane & 3;
    const int row0 = q0 + wm + cg, row1 = row0 + 8;

    float accO[8][4];
#pragma unroll
    for (int nd = 0; nd < 8; nd++)
#pragma unroll
        for (int r = 0; r < 4; r++) accO[nd][r] = 0.f;
    float m0r = -INFINITY, m1r = -INFINITY, l0 = 0.f, l1 = 0.f;

    for (int kt0 = 0; kt0 < TSEQ; kt0 += BK) {
        const bool band = (kt0 >= q0 - 191) && (kt0 <= q0 + 255);
        if (!(kt0 < keylen) && !band) continue;

        __syncthreads();
#pragma unroll
        for (int it = 0; it < 2; it++) {
            int idx = it*256 + tid;
            int r = idx >> 3, c8 = (idx & 7) * 8;
            *(uint4*)(as + KH + r*SKD + c8) = *(const uint4*)(Khp + (size_t)(kt0+r)*DHEAD + c8);
            *(uint4*)(as + KL + r*SKD + c8) = *(const uint4*)(Klp + (size_t)(kt0+r)*DHEAD + c8);
            *(uint4*)(as + VH + r*SKD + c8) = *(const uint4*)(Vhp + (size_t)r*TSEQ + kt0 + c8);
            *(uint4*)(as + VL + r*SKD + c8) = *(const uint4*)(Vlp + (size_t)r*TSEQ + kt0 + c8);
        }
        __syncthreads();

        // ---- S = Q K^T (split) -----------------------------------------
        float sc[8][4];
#pragma unroll
        for (int nt = 0; nt < 8; nt++)
#pragma unroll
            for (int r = 0; r < 4; r++) sc[nt][r] = 0.f;

#pragma unroll
        for (int ks = 0; ks < 4; ks++) {
            const int kcol = ks*16 + lhi8;
            uint32_t ah[4], al[4];
            const uint32_t ro = (uint32_t)((wm + lrow)*SKD + kcol) * 2;
            ldsm4(ah, sb + QH*2 + ro);
            ldsm4(al, sb + QL*2 + ro);
#pragma unroll
            for (int nj = 0; nj < 4; nj++) {
                const uint32_t ro2 = (uint32_t)((nj*16 + lrow)*SKD + kcol) * 2;
                uint32_t t[4], bh0[2], bh1[2], bl0[2], bl1[2];
                ldsm4(t, sb + KH*2 + ro2);
                bh0[0] = t[0]; bh1[0] = t[1]; bh0[1] = t[2]; bh1[1] = t[3];
                ldsm4(t, sb + KL*2 + ro2);
                bl0[0] = t[0]; bl1[0] = t[1]; bl0[1] = t[2]; bl1[1] = t[3];
                mma16816(sc[2*nj],   ah, bh0);
                mma16816(sc[2*nj],   al, bh0);
                mma16816(sc[2*nj],   ah, bl0);
                mma16816(sc[2*nj+1], ah, bh1);
                mma16816(sc[2*nj+1], al, bh1);
                mma16816(sc[2*nj+1], ah, bl1);
            }
        }

        // ---- mask + scale ----------------------------------------------
        const bool full = (kt0 + BK <= keylen) || (kt0 >= q0 - 1 && kt0 <= q0 + 65);
        if (full) {
#pragma unroll
            for (int nt = 0; nt < 8; nt++)
#pragma unroll
                for (int r = 0; r < 4; r++) sc[nt][r] *= 0.125f;
        } else {
#pragma unroll
            for (int nt = 0; nt < 8; nt++) {
                const int jg0 = kt0 + nt*8 + 2*ct;
#pragma unroll
                for (int r = 0; r < 4; r++) {
                    const int ig = (r < 2) ? row0 : row1;
                    const int jg = jg0 + (r & 1);
                    bool ok = (jg < keylen) ||
                              ((ig - jg <= 128) && (jg - ig <= 128));
                    sc[nt][r] = ok ? sc[nt][r] * 0.125f : -1e9f;
                }
            }
        }

        // ---- online softmax --------------------------------------------
        float rm0 = -INFINITY, rm1 = -INFINITY;
#pragma unroll
        for (int nt = 0; nt < 8; nt++) {
            rm0 = fmaxf(rm0, fmaxf(sc[nt][0], sc[nt][1]));
            rm1 = fmaxf(rm1, fmaxf(sc[nt][2], sc[nt][3]));
        }
        rm0 = fmaxf(rm0, __shfl_xor_sync(0xffffffffu, rm0, 1));
        rm0 = fmaxf(rm0, __shfl_xor_sync(0xffffffffu, rm0, 2));
        rm1 = fmaxf(rm1, __shfl_xor_sync(0xffffffffu, rm1, 1));
        rm1 = fmaxf(rm1, __shfl_xor_sync(0xffffffffu, rm1, 2));
        const float mn0 = fmaxf(m0r, rm0), mn1 = fmaxf(m1r, rm1);
        const float cr0 = __expf(m0r - mn0), cr1 = __expf(m1r - mn1);
        float rs0 = 0.f, rs1 = 0.f;
#pragma unroll
        for (int nt = 0; nt < 8; nt++) {
            sc[nt][0] = __expf(sc[nt][0] - mn0); rs0 += sc[nt][0];
            sc[nt][1] = __expf(sc[nt][1] - mn0); rs0 += sc[nt][1];
            sc[nt][2] = __expf(sc[nt][2] - mn1); rs1 += sc[nt][2];
            sc[nt][3] = __expf(sc[nt][3] - mn1); rs1 += sc[nt][3];
        }
        rs0 += __shfl_xor_sync(0xffffffffu, rs0, 1);
        rs0 += __shfl_xor_sync(0xffffffffu, rs0, 2);
        rs1 += __shfl_xor_sync(0xffffffffu, rs1, 1);
        rs1 += __shfl_xor_sync(0xffffffffu, rs1, 2);
        l0 = l0*cr0 + rs0;  m0r = mn0;
        l1 = l1*cr1 + rs1;  m1r = mn1;
#pragma unroll
        for (int nd = 0; nd < 8; nd++) {
            accO[nd][0] *= cr0; accO[nd][1] *= cr0;
            accO[nd][2] *= cr1; accO[nd][3] *= cr1;
        }

        // ---- O += P V (split, P frags reused from sc) ------------------
#pragma unroll
        for (int ksv = 0; ksv < 4; ksv++) {
            uint32_t aH[4], aL[4];
            aH[0] = pf2(sc[2*ksv][0],   sc[2*ksv][1]);
            aH[1] = pf2(sc[2*ksv][2],   sc[2*ksv][3]);
            aH[2] = pf2(sc[2*ksv+1][0], sc[2*ksv+1][1]);
            aH[3] = pf2(sc[2*ksv+1][2], sc[2*ksv+1][3]);
            aL[0] = plo2(sc[2*ksv][0],   sc[2*ksv][1],   aH[0]);
            aL[1] = plo2(sc[2*ksv][2],   sc[2*ksv][3],   aH[1]);
            aL[2] = plo2(sc[2*ksv+1][0], sc[2*ksv+1][1], aH[2]);
            aL[3] = plo2(sc[2*ksv+1][2], sc[2*ksv+1][3], aH[3]);
            const int kcol = ksv*16 + lhi8;
#pragma unroll
            for (int dj = 0; dj < 4; dj++) {
                const uint32_t ro = (uint32_t)((dj*16 + lrow)*SKD + kcol) * 2;
                uint32_t t[4], vh0[2], vh1[2], vl0[2], vl1[2];
                ldsm4(t, sb + VH*2 + ro);
                vh0[0] = t[0]; vh1[0] = t[1]; vh0[1] = t[2]; vh1[1] = t[3];
                ldsm4(t, sb + VL*2 + ro);
                vl0[0] = t[0]; vl1[0] = t[1]; vl0[1] = t[2]; vl1[1] = t[3];
                mma16816(accO[2*dj],   aH, vh0);
                mma16816(accO[2*dj],   aL, vh0);
                mma16816(accO[2*dj],   aH, vl0);
                mma16816(accO[2*dj+1], aH, vh1);
                mma16816(accO[2*dj+1], aL, vh1);
                mma16816(accO[2*dj+1], aH, vl1);
            }
        }
    }

    // ---- epilogue: write bf16 hi/lo y directly -------------------------
    const float i0 = 1.f / l0, i1 = 1.f / l1;
#pragma unroll
    for (int nd = 0; nd < 8; nd++) {
        const int d = h*DHEAD + nd*8 + 2*ct;
        const float a0 = accO[nd][0]*i0, a1 = accO[nd][1]*i0;
        const float b0 = accO[nd][2]*i1, b1 = accO[nd][3]*i1;
        const size_t i0x = (size_t)(row0*NBATCH + n)*CDIM + d;
        const size_t i1x = (size_t)(row1*NBATCH + n)*CDIM + d;
        uint32_t hp = pf2(a0, a1);
        *(uint32_t*)(g_yh + i0x) = hp;
        *(uint32_t*)(g_yl + i0x) = plo2(a0, a1, hp);
        hp = pf2(b0, b1);
        *(uint32_t*)(g_yh + i1x) = hp;
        *(uint32_t*)(g_yl + i1x) = plo2(b0, b1, hp);
    }
}

// ---------------------------------------------------------------------------
extern "C" void kernel_launch(void* const* d_in, const int* in_sizes, int n_in,
                              void* d_out, int out_size) {
    const float* q  = (const float*)d_in[0];
    const float* k  = (const float*)d_in[1];
    const float* v  = (const float*)d_in[2];
    const float* Wq = (const float*)d_in[3];
    const float* bq = (const float*)d_in[4];
    const float* Wk = (const float*)d_in[5];
    const float* bk = (const float*)d_in[6];
    const float* Wv = (const float*)d_in[7];
    const float* bv = (const float*)d_in[8];
    const float* Wo = (const float*)d_in[9];
    const float* bo = (const float*)d_in[10];
    const int* keylen = (const int*)d_in[11];
    float* out = (float*)d_out;

    cudaFuncSetAttribute(proj3_tc, cudaFuncAttributeMaxDynamicSharedMemorySize, SMEM_G);
    cudaFuncSetAttribute(oproj_tc, cudaFuncAttributeMaxDynamicSharedMemorySize, SMEM_G);
    cudaFuncSetAttribute(attn_tc,  cudaFuncAttributeMaxDynamicSharedMemorySize, SMEM_A);

    // pre-split weights once (removes 32x-redundant conversion from GEMM loops)
    split_w<<<dim3(CDIM*CDIM/4/256, 1, 4), 256>>>(Wq, Wk, Wv, Wo);

    // q/k/v projections: inputs fused-split, weights pre-split
    proj3_tc<<<dim3(CDIM/128, MROWS/128, 3), 256, SMEM_G>>>(
        q, k, v, bq, bk, bv);

    // tensor-core masked flash attention -> y bf16 split
    attn_tc<<<dim3(TSEQ/BQ, NHEAD, NBATCH), 256, SMEM_A>>>(keylen);

    // output projection (both operands pre-split)
    oproj_tc<<<dim3(CDIM/128, MROWS/128, 1), 256, SMEM_G>>>(bo, out);
}

// round 13
// speedup vs baseline: 1.0129x; 1.0129x over previous
#include <cuda_runtime.h>
#include <cuda_bf16.h>
#include <math.h>
#include <stdint.h>

#define TSEQ 2048
#define NBATCH 2
#define CDIM 1024
#define NHEAD 16
#define DHEAD 64
#define MROWS (TSEQ*NBATCH)   // 4096

#define KCH 64                // gemm k-chunk held in smem
#define SKA 72                // smem row stride in halves (bank-conflict-free)
#define A_H (128*SKA)         // halves per A tile (128 rows)
#define B_H (64*SKA)          // halves per B tile (64 rows)
#define SMEM_G ((2*A_H + 2*B_H)*2)   // 55296 bytes
#define VPITCH 129            // fp32 pitch for V-transpose epilogue (64*129*4=33KB)

// attention tiling (single-buffered, high occupancy)
#define BQ 128
#define BK 64
#define SKD 72
#define SMEM_A ((2*BQ*SKD + 2*BK*SKD + 2*DHEAD*SKD)*2)

// ---------------- scratch (__device__ globals; no allocation allowed) -------
__device__ __align__(256) __nv_bfloat16 g_wh[4u*CDIM*CDIM];   // pre-split weights
__device__ __align__(256) __nv_bfloat16 g_wl[4u*CDIM*CDIM];
__device__ __align__(256) __nv_bfloat16 g_yh[MROWS*CDIM];
__device__ __align__(256) __nv_bfloat16 g_yl[MROWS*CDIM];
__device__ __align__(256) __nv_bfloat16 g_aqh[NBATCH*NHEAD*TSEQ*DHEAD];
__device__ __align__(256) __nv_bfloat16 g_aql[NBATCH*NHEAD*TSEQ*DHEAD];
__device__ __align__(256) __nv_bfloat16 g_akh[NBATCH*NHEAD*TSEQ*DHEAD];
__device__ __align__(256) __nv_bfloat16 g_akl[NBATCH*NHEAD*TSEQ*DHEAD];
__device__ __align__(256) __nv_bfloat16 g_avth[NBATCH*NHEAD*DHEAD*TSEQ]; // [d][t]
__device__ __align__(256) __nv_bfloat16 g_avtl[NBATCH*NHEAD*DHEAD*TSEQ];

// ---------------- PTX helpers ----------------------------------------------
__device__ __forceinline__ uint32_t smem_u32(const void* p) {
    uint32_t r;
    asm("{ .reg .u64 t; cvta.to.shared.u64 t, %1; cvt.u32.u64 %0, t; }"
        : "=r"(r) : "l"(p));
    return r;
}

__device__ __forceinline__ void ldsm4(uint32_t* r, uint32_t addr) {
    asm volatile("ldmatrix.sync.aligned.m8n8.x4.shared.b16 {%0,%1,%2,%3}, [%4];"
                 : "=r"(r[0]), "=r"(r[1]), "=r"(r[2]), "=r"(r[3]) : "r"(addr));
}

__device__ __forceinline__ void mma16816(float* c, const uint32_t* a, const uint32_t* b) {
    asm volatile("mma.sync.aligned.m16n8k16.row.col.f32.bf16.bf16.f32 "
                 "{%0,%1,%2,%3}, {%4,%5,%6,%7}, {%8,%9}, {%0,%1,%2,%3};"
                 : "+f"(c[0]), "+f"(c[1]), "+f"(c[2]), "+f"(c[3])
                 : "r"(a[0]), "r"(a[1]), "r"(a[2]), "r"(a[3]),
                   "r"(b[0]), "r"(b[1]));
}

__device__ __forceinline__ uint32_t pf2(float lo, float hi) {  // pack bf16x2 {lo,hi}
    uint32_t r;
    asm("cvt.rn.bf16x2.f32 %0, %1, %2;" : "=r"(r) : "f"(hi), "f"(lo));
    return r;
}
__device__ __forceinline__ uint32_t plo2(float x0, float x1, uint32_t hp) {
    float h0 = __uint_as_float(hp << 16);
    float h1 = __uint_as_float(hp & 0xffff0000u);
    return pf2(x0 - h0, x1 - h1);
}

// ---------------- tile loaders (ROWS x 64) ----------------------------------
template<int ROWS>
__device__ __forceinline__ void load_split_f32(const float* __restrict__ src,
                                               __nv_bfloat16* smh, __nv_bfloat16* sml,
                                               int k0, int tid)
{
#pragma unroll
    for (int it = 0; it < ROWS/32; it++) {
        const int idx = it*256 + tid;
        const int row = idx >> 3;
        const int c8  = (idx & 7) * 8;
        const float4* p = (const float4*)(src + (size_t)row * CDIM + k0 + c8);
        float4 a = p[0], b = p[1];
        uint4 hi, lo;
        hi.x = pf2(a.x, a.y); lo.x = plo2(a.x, a.y, hi.x);
        hi.y = pf2(a.z, a.w); lo.y = plo2(a.z, a.w, hi.y);
        hi.z = pf2(b.x, b.y); lo.z = plo2(b.x, b.y, hi.z);
        hi.w = pf2(b.z, b.w); lo.w = plo2(b.z, b.w, hi.w);
        *(uint4*)(smh + row*SKA + c8) = hi;
        *(uint4*)(sml + row*SKA + c8) = lo;
    }
}

template<int ROWS>
__device__ __forceinline__ void load_pre(const __nv_bfloat16* __restrict__ sh,
                                         const __nv_bfloat16* __restrict__ sl,
                                         __nv_bfloat16* smh, __nv_bfloat16* sml,
                                         int k0, int tid)
{
#pragma unroll
    for (int it = 0; it < ROWS/32; it++) {
        const int idx = it*256 + tid;
        const int row = idx >> 3;
        const int c8  = (idx & 7) * 8;
        const size_t go = (size_t)row * CDIM + k0 + c8;
        const int so = row*SKA + c8;
        *(uint4*)(smh + so) = *(const uint4*)(sh + go);
        *(uint4*)(sml + so) = *(const uint4*)(sl + go);
    }
}

// ---------------- bf16-split GEMM, 128x64 tile, 3 CTA/SM --------------------
// 8 warps as 4(m) x 2(n); warp tile 32x32.
// MODE 0: fp32 Of[m*CDIM+c];  MODE 2: bf16 split head layout;
// MODE 3: V -> transposed bf16 split [n][h][d][t] via smem transpose.
template<int MODE, bool AF32>
__device__ void gemm_mma(const float* __restrict__ Af,
                         const __nv_bfloat16* __restrict__ Ahh,
                         const __nv_bfloat16* __restrict__ Alo,
                         const __nv_bfloat16* __restrict__ Bhh,
                         const __nv_bfloat16* __restrict__ Blo,
                         const float* __restrict__ bias,
                         float* __restrict__ Of,
                         __nv_bfloat16* __restrict__ Oh,
                         __nv_bfloat16* __restrict__ Ol)
{
    extern __shared__ char dsm[];
    __nv_bfloat16* sm = (__nv_bfloat16*)dsm;
    const int tid  = threadIdx.x;
    const int lane = tid & 31;
    const int wid  = tid >> 5;
    const int m0   = blockIdx.y * 128;
    const int n0   = blockIdx.x * 64;
    const int wm   = (wid >> 1) * 32;   // 0,32,64,96
    const int wn   = (wid & 1) * 32;    // 0,32

    const uint32_t sbase = smem_u32(sm);
    const uint32_t AHo = 0, ALo = A_H*2, BHo = 2*A_H*2, BLo = (2*A_H + B_H)*2;

    float acc[2][4][4];
#pragma unroll
    for (int mi = 0; mi < 2; mi++)
#pragma unroll
        for (int ni = 0; ni < 4; ni++)
#pragma unroll
            for (int r = 0; r < 4; r++) acc[mi][ni][r] = 0.f;

    const int lrow = lane & 15;
    const int lhi8 = (lane >> 4) * 8;

    for (int k0 = 0; k0 < CDIM; k0 += KCH) {
        __syncthreads();
        if (AF32) load_split_f32<128>(Af + (size_t)m0*CDIM, sm, sm + A_H, k0, tid);
        else      load_pre<128>(Ahh + (size_t)m0*CDIM, Alo + (size_t)m0*CDIM,
                                sm, sm + A_H, k0, tid);
        load_pre<64>(Bhh + (size_t)n0*CDIM, Blo + (size_t)n0*CDIM,
                     sm + 2*A_H, sm + 2*A_H + B_H, k0, tid);
        __syncthreads();

#pragma unroll
        for (int ks = 0; ks < KCH/16; ks++) {
            const int kcol = ks*16 + lhi8;
            uint32_t ah[2][4], al[2][4], bh[4][2], bl[4][2];
#pragma unroll
            for (int mi = 0; mi < 2; mi++) {
                const uint32_t ro = (uint32_t)((wm + mi*16 + lrow)*SKA + kcol) * 2;
                ldsm4(ah[mi], sbase + AHo + ro);
                ldsm4(al[mi], sbase + ALo + ro);
            }
#pragma unroll
            for (int nj = 0; nj < 2; nj++) {
                const uint32_t ro = (uint32_t)((wn + nj*16 + lrow)*SKA + kcol) * 2;
                uint32_t t[4];
                ldsm4(t, sbase + BHo + ro);
                bh[2*nj][0] = t[0]; bh[2*nj+1][0] = t[1];
                bh[2*nj][1] = t[2]; bh[2*nj+1][1] = t[3];
                ldsm4(t, sbase + BLo + ro);
                bl[2*nj][0] = t[0]; bl[2*nj+1][0] = t[1];
                bl[2*nj][1] = t[2]; bl[2*nj+1][1] = t[3];
            }
#pragma unroll
            for (int mi = 0; mi < 2; mi++)
#pragma unroll
                for (int ni = 0; ni < 4; ni++) {
                    mma16816(acc[mi][ni], ah[mi], bh[ni]);
                    mma16816(acc[mi][ni], al[mi], bh[ni]);
                    mma16816(acc[mi][ni], ah[mi], bl[ni]);
                }
        }
    }

    const int cg = lane >> 2;
    const int ct = lane & 3;

    if (MODE == 3) {
        // ---- V epilogue: smem transpose -> [n][h][d][t] bf16 hi/lo ---------
        __syncthreads();                       // all smem tile reads done
        float* sv = (float*)dsm;               // 64 x VPITCH fp32 (33 KB)
#pragma unroll
        for (int mi = 0; mi < 2; mi++) {
#pragma unroll
            for (int ni = 0; ni < 4; ni++) {
                const int c = wn + ni*8 + ct*2;
                const float b0 = bias[n0 + c], b1 = bias[n0 + c + 1];
#pragma unroll
                for (int half = 0; half < 2; half++) {
                    const int m  = wm + mi*16 + cg + half*8;
                    const int nb = m & 1, tl = m >> 1;
                    sv[(c  )*VPITCH + nb*64 + tl] = acc[mi][ni][half*2+0] + b0;
                    sv[(c+1)*VPITCH + nb*64 + tl] = acc[mi][ni][half*2+1] + b1;
                }
            }
        }
        __syncthreads();
        // readout: 64 cols x 2 nb x 2 halves-of-64 = 256 segments of 32
        const int c   = tid >> 2;
        const int nb  = (tid >> 1) & 1;
        const int sg  = tid & 1;               // which 32 of the 64 t-values
        const int gcol = n0 + c, hh = gcol >> 6, d = gcol & 63;
        const size_t base = ((size_t)(nb*NHEAD + hh)*DHEAD + d)*TSEQ + (m0 >> 1) + sg*32;
        const float* row = sv + c*VPITCH + nb*64 + sg*32;
#pragma unroll
        for (int j = 0; j < 4; j++) {
            const float x0 = row[8*j+0], x1 = row[8*j+1], x2 = row[8*j+2], x3 = row[8*j+3];
            const float x4 = row[8*j+4], x5 = row[8*j+5], x6 = row[8*j+6], x7 = row[8*j+7];
            uint4 hv, lv;
            hv.x = pf2(x0, x1); lv.x = plo2(x0, x1, hv.x);
            hv.y = pf2(x2, x3); lv.y = plo2(x2, x3, hv.y);
            hv.z = pf2(x4, x5); lv.z = plo2(x4, x5, hv.z);
            hv.w = pf2(x6, x7); lv.w = plo2(x6, x7, hv.w);
            *(uint4*)(Oh + base + 8*j) = hv;
            *(uint4*)(Ol + base + 8*j) = lv;
        }
        return;
    }

#pragma unroll
    for (int mi = 0; mi < 2; mi++) {
#pragma unroll
        for (int ni = 0; ni < 4; ni++) {
            const int c = n0 + wn + ni*8 + ct*2;
            const float b0 = bias[c], b1 = bias[c+1];
#pragma unroll
            for (int half = 0; half < 2; half++) {
                const int m = m0 + wm + mi*16 + cg + half*8;
                const float v0 = acc[mi][ni][half*2+0] + b0;
                const float v1 = acc[mi][ni][half*2+1] + b1;
                if (MODE == 0) {
                    *(float2*)(Of + (size_t)m*CDIM + c) = make_float2(v0, v1);
                } else {   // MODE == 2
                    const int t = m >> 1, nb = m & 1;
                    const int h = c >> 6, d = c & 63;
                    const size_t idx = ((size_t)(nb*NHEAD + h)*TSEQ + t)*DHEAD + d;
                    const uint32_t hp = pf2(v0, v1);
                    *(uint32_t*)(Oh + idx) = hp;
                    *(uint32_t*)(Ol + idx) = plo2(v0, v1, hp);
                }
            }
        }
    }
}

__global__ __launch_bounds__(256, 3) void proj3_tc(
    const float* __restrict__ q,  const float* __restrict__ k,  const float* __restrict__ v,
    const float* __restrict__ bq, const float* __restrict__ bk, const float* __restrict__ bv)
{
    const int z = blockIdx.z;
    const float* A    = (z == 0) ? q  : (z == 1) ? k  : v;
    const float* bias = (z == 0) ? bq : (z == 1) ? bk : bv;
    const __nv_bfloat16* Bh = g_wh + (size_t)z * CDIM * CDIM;
    const __nv_bfloat16* Bl = g_wl + (size_t)z * CDIM * CDIM;
    if (z == 2) {
        gemm_mma<3, true>(A, nullptr, nullptr, Bh, Bl, bias,
                          nullptr, g_avth, g_avtl);
    } else {
        __nv_bfloat16* oh = (z == 0) ? g_aqh : g_akh;
        __nv_bfloat16* ol = (z == 0) ? g_aql : g_akl;
        gemm_mma<2, true>(A, nullptr, nullptr, Bh, Bl, bias,
                          nullptr, oh, ol);
    }
}

__global__ __launch_bounds__(256, 3) void oproj_tc(const float* __restrict__ bo,
                                                   float* __restrict__ out)
{
    gemm_mma<0, false>(nullptr, g_yh, g_yl,
                       g_wh + (size_t)3*CDIM*CDIM, g_wl + (size_t)3*CDIM*CDIM,
                       bo, out, nullptr, nullptr);
}

// ---------------- weight pre-split (runs once per launch) -------------------
__global__ __launch_bounds__(256) void split_w(const float* __restrict__ Wq,
                                               const float* __restrict__ Wk,
                                               const float* __restrict__ Wv,
                                               const float* __restrict__ Wo)
{
    const int z = blockIdx.z;
    const float* s = (z == 0) ? Wq : (z == 1) ? Wk : (z == 2) ? Wv : Wo;
    const size_t off = (size_t)z * CDIM * CDIM;
    const size_t i = ((size_t)blockIdx.x * blockDim.x + threadIdx.x) * 4;
    float4 vv = *(const float4*)(s + i);
    uint2 hi, lo;
    hi.x = pf2(vv.x, vv.y); lo.x = plo2(vv.x, vv.y, hi.x);
    hi.y = pf2(vv.z, vv.w); lo.y = plo2(vv.z, vv.w, hi.y);
    *(uint2*)(g_wh + off + i) = hi;
    *(uint2*)(g_wl + off + i) = lo;
}

// ---------------- tensor-core flash attention (single-buffered) -------------
__global__ __launch_bounds__(256) void attn_tc(const int* __restrict__ key_length)
{
    extern __shared__ __nv_bfloat16 as[];
    const int QH = 0, QL = BQ*SKD, KH = 2*BQ*SKD, KL = KH + BK*SKD,
              VH = KL + BK*SKD, VL = VH + DHEAD*SKD;

    const int tid = threadIdx.x, lane = tid & 31, wid = tid >> 5;
    const int n = blockIdx.z, h = blockIdx.y;
    const int q0 = blockIdx.x * BQ;
    const int keylen = key_length[n];
    const size_t hb = (size_t)(n*NHEAD + h);

    const __nv_bfloat16* Qhp = g_aqh + hb*TSEQ*DHEAD;
    const __nv_bfloat16* Qlp = g_aql + hb*TSEQ*DHEAD;
    const __nv_bfloat16* Khp = g_akh + hb*TSEQ*DHEAD;
    const __nv_bfloat16* Klp = g_akl + hb*TSEQ*DHEAD;
    const __nv_bfloat16* Vhp = g_avth + hb*DHEAD*TSEQ;
    const __nv_bfloat16* Vlp = g_avtl + hb*DHEAD*TSEQ;

    // load Q once (128x64 hi+lo)
#pragma unroll
    for (int it = 0; it < 4; it++) {
        int idx = it*256 + tid;
        int r = idx >> 3, c8 = (idx & 7) * 8;
        *(uint4*)(as + QH + r*SKD + c8) = *(const uint4*)(Qhp + (size_t)(q0+r)*DHEAD + c8);
        *(uint4*)(as + QL + r*SKD + c8) = *(const uint4*)(Qlp + (size_t)(q0+r)*DHEAD + c8);
    }

    const uint32_t sb = smem_u32(as);
    const int wm = wid * 16;
    const int lrow = lane & 15, lhi8 = (lane >> 4) * 8;
    const int cg = lane >> 2, ct = lane & 3;
    const int row0 = q0 + wm + cg, row1 = row0 + 8;

    float accO[8][4];
#pragma unroll
    for (int nd = 0; nd < 8; nd++)
#pragma unroll
        for (int r = 0; r < 4; r++) accO[nd][r] = 0.f;
    float m0r = -INFINITY, m1r = -INFINITY, l0 = 0.f, l1 = 0.f;

    for (int kt0 = 0; kt0 < TSEQ; kt0 += BK) {
        const bool band = (kt0 >= q0 - 191) && (kt0 <= q0 + 255);
        if (!(kt0 < keylen) && !band) continue;

        __syncthreads();
#pragma unroll
        for (int it = 0; it < 2; it++) {
            int idx = it*256 + tid;
            int r = idx >> 3, c8 = (idx & 7) * 8;
            *(uint4*)(as + KH + r*SKD + c8) = *(const uint4*)(Khp + (size_t)(kt0+r)*DHEAD + c8);
            *(uint4*)(as + KL + r*SKD + c8) = *(const uint4*)(Klp + (size_t)(kt0+r)*DHEAD + c8);
            *(uint4*)(as + VH + r*SKD + c8) = *(const uint4*)(Vhp + (size_t)r*TSEQ + kt0 + c8);
            *(uint4*)(as + VL + r*SKD + c8) = *(const uint4*)(Vlp + (size_t)r*TSEQ + kt0 + c8);
        }
        __syncthreads();

        // ---- S = Q K^T (split) -----------------------------------------
        float sc[8][4];
#pragma unroll
        for (int nt = 0; nt < 8; nt++)
#pragma unroll
            for (int r = 0; r < 4; r++) sc[nt][r] = 0.f;

#pragma unroll
        for (int ks = 0; ks < 4; ks++) {
            const int kcol = ks*16 + lhi8;
            uint32_t ah[4], al[4];
            const uint32_t ro = (uint32_t)((wm + lrow)*SKD + kcol) * 2;
            ldsm4(ah, sb + QH*2 + ro);
            ldsm4(al, sb + QL*2 + ro);
#pragma unroll
            for (int nj = 0; nj < 4; nj++) {
                const uint32_t ro2 = (uint32_t)((nj*16 + lrow)*SKD + kcol) * 2;
                uint32_t t[4], bh0[2], bh1[2], bl0[2], bl1[2];
                ldsm4(t, sb + KH*2 + ro2);
                bh0[0] = t[0]; bh1[0] = t[1]; bh0[1] = t[2]; bh1[1] = t[3];
                ldsm4(t, sb + KL*2 + ro2);
                bl0[0] = t[0]; bl1[0] = t[1]; bl0[1] = t[2]; bl1[1] = t[3];
                mma16816(sc[2*nj],   ah, bh0);
                mma16816(sc[2*nj],   al, bh0);
                mma16816(sc[2*nj],   ah, bl0);
                mma16816(sc[2*nj+1], ah, bh1);
                mma16816(sc[2*nj+1], al, bh1);
                mma16816(sc[2*nj+1], ah, bl1);
            }
        }

        // ---- mask + scale ----------------------------------------------
        const bool full = (kt0 + BK <= keylen) || (kt0 >= q0 - 1 && kt0 <= q0 + 65);
        if (full) {
#pragma unroll
            for (int nt = 0; nt < 8; nt++)
#pragma unroll
                for (int r = 0; r < 4; r++) sc[nt][r] *= 0.125f;
        } else {
#pragma unroll
            for (int nt = 0; nt < 8; nt++) {
                const int jg0 = kt0 + nt*8 + 2*ct;
#pragma unroll
                for (int r = 0; r < 4; r++) {
                    const int ig = (r < 2) ? row0 : row1;
                    const int jg = jg0 + (r & 1);
                    bool ok = (jg < keylen) ||
                              ((ig - jg <= 128) && (jg - ig <= 128));
                    sc[nt][r] = ok ? sc[nt][r] * 0.125f : -1e9f;
                }
            }
        }

        // ---- online softmax --------------------------------------------
        float rm0 = -INFINITY, rm1 = -INFINITY;
#pragma unroll
        for (int nt = 0; nt < 8; nt++) {
            rm0 = fmaxf(rm0, fmaxf(sc[nt][0], sc[nt][1]));
            rm1 = fmaxf(rm1, fmaxf(sc[nt][2], sc[nt][3]));
        }
        rm0 = fmaxf(rm0, __shfl_xor_sync(0xffffffffu, rm0, 1));
        rm0 = fmaxf(rm0, __shfl_xor_sync(0xffffffffu, rm0, 2));
        rm1 = fmaxf(rm1, __shfl_xor_sync(0xffffffffu, rm1, 1));
        rm1 = fmaxf(rm1, __shfl_xor_sync(0xffffffffu, rm1, 2));
        const float mn0 = fmaxf(m0r, rm0), mn1 = fmaxf(m1r, rm1);
        const float cr0 = __expf(m0r - mn0), cr1 = __expf(m1r - mn1);
        float rs0 = 0.f, rs1 = 0.f;
#pragma unroll
        for (int nt = 0; nt < 8; nt++) {
            sc[nt][0] = __expf(sc[nt][0] - mn0); rs0 += sc[nt][0];
            sc[nt][1] = __expf(sc[nt][1] - mn0); rs0 += sc[nt][1];
            sc[nt][2] = __expf(sc[nt][2] - mn1); rs1 += sc[nt][2];
            sc[nt][3] = __expf(sc[nt][3] - mn1); rs1 += sc[nt][3];
        }
        rs0 += __shfl_xor_sync(0xffffffffu, rs0, 1);
        rs0 += __shfl_xor_sync(0xffffffffu, rs0, 2);
        rs1 += __shfl_xor_sync(0xffffffffu, rs1, 1);
        rs1 += __shfl_xor_sync(0xffffffffu, rs1, 2);
        l0 = l0*cr0 + rs0;  m0r = mn0;
        l1 = l1*cr1 + rs1;  m1r = mn1;
#pragma unroll
        for (int nd = 0; nd < 8; nd++) {
            accO[nd][0] *= cr0; accO[nd][1] *= cr0;
            accO[nd][2] *= cr1; accO[nd][3] *= cr1;
        }

        // ---- O += P V (split, P frags reused from sc) ------------------
#pragma unroll
        for (int ksv = 0; ksv < 4; ksv++) {
            uint32_t aH[4], aL[4];
            aH[0] = pf2(sc[2*ksv][0],   sc[2*ksv][1]);
            aH[1] = pf2(sc[2*ksv][2],   sc[2*ksv][3]);
            aH[2] = pf2(sc[2*ksv+1][0], sc[2*ksv+1][1]);
            aH[3] = pf2(sc[2*ksv+1][2], sc[2*ksv+1][3]);
            aL[0] = plo2(sc[2*ksv][0],   sc[2*ksv][1],   aH[0]);
            aL[1] = plo2(sc[2*ksv][2],   sc[2*ksv][3],   aH[1]);
            aL[2] = plo2(sc[2*ksv+1][0], sc[2*ksv+1][1], aH[2]);
            aL[3] = plo2(sc[2*ksv+1][2], sc[2*ksv+1][3], aH[3]);
            const int kcol = ksv*16 + lhi8;
#pragma unroll
            for (int dj = 0; dj < 4; dj++) {
                const uint32_t ro = (uint32_t)((dj*16 + lrow)*SKD + kcol) * 2;
                uint32_t t[4], vh0[2], vh1[2], vl0[2], vl1[2];
                ldsm4(t, sb + VH*2 + ro);
                vh0[0] = t[0]; vh1[0] = t[1]; vh0[1] = t[2]; vh1[1] = t[3];
                ldsm4(t, sb + VL*2 + ro);
                vl0[0] = t[0]; vl1[0] = t[1]; vl0[1] = t[2]; vl1[1] = t[3];
                mma16816(accO[2*dj],   aH, vh0);
                mma16816(accO[2*dj],   aL, vh0);
                mma16816(accO[2*dj],   aH, vl0);
                mma16816(accO[2*dj+1], aH, vh1);
                mma16816(accO[2*dj+1], aL, vh1);
                mma16816(accO[2*dj+1], aH, vl1);
            }
        }
    }

    // ---- epilogue: write bf16 hi/lo y directly -------------------------
    const float i0 = 1.f / l0, i1 = 1.f / l1;
#pragma unroll
    for (int nd = 0; nd < 8; nd++) {
        const int d = h*DHEAD + nd*8 + 2*ct;
        const float a0 = accO[nd][0]*i0, a1 = accO[nd][1]*i0;
        const float b0 = accO[nd][2]*i1, b1 = accO[nd][3]*i1;
        const size_t i0x = (size_t)(row0*NBATCH + n)*CDIM + d;
        const size_t i1x = (size_t)(row1*NBATCH + n)*CDIM + d;
        uint32_t hp = pf2(a0, a1);
        *(uint32_t*)(g_yh + i0x) = hp;
        *(uint32_t*)(g_yl + i0x) = plo2(a0, a1, hp);
        hp = pf2(b0, b1);
        *(uint32_t*)(g_yh + i1x) = hp;
        *(uint32_t*)(g_yl + i1x) = plo2(b0, b1, hp);
    }
}

// ---------------------------------------------------------------------------
extern "C" void kernel_launch(void* const* d_in, const int* in_sizes, int n_in,
                              void* d_out, int out_size) {
    const float* q  = (const float*)d_in[0];
    const float* k  = (const float*)d_in[1];
    const float* v  = (const float*)d_in[2];
    const float* Wq = (const float*)d_in[3];
    const float* bq = (const float*)d_in[4];
    const float* Wk = (const float*)d_in[5];
    const float* bk = (const float*)d_in[6];
    const float* Wv = (const float*)d_in[7];
    const float* bv = (const float*)d_in[8];
    const float* Wo = (const float*)d_in[9];
    const float* bo = (const float*)d_in[10];
    const int* keylen = (const int*)d_in[11];
    float* out = (float*)d_out;

    cudaFuncSetAttribute(proj3_tc, cudaFuncAttributeMaxDynamicSharedMemorySize, SMEM_G);
    cudaFuncSetAttribute(oproj_tc, cudaFuncAttributeMaxDynamicSharedMemorySize, SMEM_G);
    cudaFuncSetAttribute(attn_tc,  cudaFuncAttributeMaxDynamicSharedMemorySize, SMEM_A);

    // pre-split weights once
    split_w<<<dim3(CDIM*CDIM/4/256, 1, 4), 256>>>(Wq, Wk, Wv, Wo);

    // q/k/v projections: 128x64 tiles, 3 CTAs/SM
    proj3_tc<<<dim3(CDIM/64, MROWS/128, 3), 256, SMEM_G>>>(
        q, k, v, bq, bk, bv);

    // tensor-core masked flash attention -> y bf16 split
    attn_tc<<<dim3(TSEQ/BQ, NHEAD, NBATCH), 256, SMEM_A>>>(keylen);

    // output projection
    oproj_tc<<<dim3(CDIM/64, MROWS/128, 1), 256, SMEM_G>>>(bo, out);
}